// round 7
// baseline (speedup 1.0000x reference)
#include <cuda_runtime.h>
#include <math.h>

// Problem constants (fixed by the dataset)
#define Bq   2
#define Nc   6
#define Cc   256
#define Mq   900
#define EPSF 1e-5f

#define H0 116
#define W0 200
#define H1 58
#define W1 100
#define H2 29
#define W2 50
#define H3 15
#define W3 25

// ---------- global scratch: per-(query,camera) sampling metadata ----------
// g_meta_w : prescaled bilinear weights (w * 0.25 / (cnt + eps))
// g_meta_x : {xi as int bits, yi as int bits, valid (1.0/0.0), unused}
__device__ float4 g_meta_w[Bq * Mq * Nc];
__device__ float4 g_meta_x[Bq * Mq * Nc];

// =========================================================================
//  Kernel A: L0 + L1 gathers (vectorized, warp-uniform meta) + meta export
// =========================================================================
__device__ __forceinline__ float pick4(float4 q, int i)
{
    float r = q.w;
    r = (i == 2) ? q.z : r;
    r = (i == 1) ? q.y : r;
    r = (i == 0) ? q.x : r;
    return r;
}

// V=4 meta builder (one thread per camera)
template <int H, int W>
__device__ __forceinline__ void mk_meta4(int bnC, float x0f, float y0f,
                                         int xi, int yi,
                                         int& off, int& i0o, int& spo, int& flags)
{
    bool bx0 = (x0f >= 0.0f)  & (x0f <= (float)(W - 1));
    bool bx1 = (x0f >= -1.0f) & (x0f <= (float)(W - 2));
    bool by0 = (y0f >= 0.0f)  & (y0f <= (float)(H - 1));
    bool by1 = (y0f >= -1.0f) & (y0f <= (float)(H - 2));

    int a = xi & ~3;
    a = (a < 0) ? 0 : a;
    a = (a > W - 4) ? (W - 4) : a;
    int  i0   = xi - a;
    bool sp   = (i0 >= 3);
    bool bxv  = bx1 & !sp;
    bool anyx = bx0 | bxv;
    bool spu  = bx1 & sp;
    int f = 0;
    f |= (by0 & anyx) ? 1  : 0;
    f |= (by1 & anyx) ? 2  : 0;
    f |= bx0          ? 4  : 0;
    f |= bxv          ? 8  : 0;
    f |= (spu & by0)  ? 16 : 0;
    f |= (spu & by1)  ? 32 : 0;
    flags = f;
    off = bnC * (H * W) + yi * W + a;
    i0o = i0;
    spo = bnC * (H * W) + yi * W + xi + 1;
}

template <int H, int W>
__device__ __forceinline__ float use_meta4(const float* __restrict__ f, int c,
                                           int off, int i0, int spo, int flags,
                                           float w00, float w10, float w01, float w11)
{
    float v = 0.0f;
    const float* p = f + c * (H * W) + off;
    if (flags & 1) {
        float4 q = __ldg((const float4*)p);
        if (flags & 4) v += w00 * pick4(q, i0);
        if (flags & 8) v += w10 * pick4(q, i0 + 1);
    }
    if (flags & 2) {
        float4 q = __ldg((const float4*)(p + W));
        if (flags & 4) v += w01 * pick4(q, i0);
        if (flags & 8) v += w11 * pick4(q, i0 + 1);
    }
    if (flags & 16) v += w10 * __ldg(f + c * (H * W) + spo);
    if (flags & 32) v += w11 * __ldg(f + c * (H * W) + spo + W);
    return v;
}

__global__ void __launch_bounds__(Cc)
kernelA(const float* __restrict__ f0,
        const float* __restrict__ f1,
        const float* __restrict__ refp,
        const float* __restrict__ l2i,
        float* __restrict__ out)
{
    __shared__ int   s_valid[Nc];
    __shared__ float s_w[Nc][4];
    __shared__ int   s_off[Nc][2], s_i0[Nc][2], s_spo[Nc][2], s_flags[Nc][2];

    int bm = blockIdx.x;
    int b  = bm / Mq;
    int c  = threadIdx.x;

    float rw0 = 0, rw1 = 0, rw2 = 0, rw3 = 0;
    int   rxi = 0, ryi = 0, rvalid = 0;

    if (c < Nc) {
        int n = c;
        const float* rp = refp + bm * 3;
        float rx = rp[0] * 122.4f - 61.2f;
        float ry = rp[1] * 122.4f - 61.2f;
        float rz = rp[2] * 20.0f  - 10.0f;

        const float* Mt = l2i + (b * Nc + n) * 16;
        float c0 = Mt[0] * rx + Mt[1] * ry + Mt[2]  * rz + Mt[3];
        float c1 = Mt[4] * rx + Mt[5] * ry + Mt[6]  * rz + Mt[7];
        float c2 = Mt[8] * rx + Mt[9] * ry + Mt[10] * rz + Mt[11];

        rvalid = (c2 > EPSF) ? 1 : 0;
        s_valid[n] = rvalid;

        if (rvalid) {
            float rcp = __fdividef(1.0f, c2 + EPSF);
            // grid-sample normalization cancels: pixel = p - 0.5 at EVERY level
            float x = c0 * rcp - 0.5f;
            float y = c1 * rcp - 0.5f;
            float x0f = floorf(x);
            float y0f = floorf(y);
            float wx1 = x - x0f, wx0 = 1.0f - wx1;
            float wy1 = y - y0f, wy0 = 1.0f - wy1;
            rw0 = wx0 * wy0; rw1 = wx1 * wy0;
            rw2 = wx0 * wy1; rw3 = wx1 * wy1;
            s_w[n][0] = rw0; s_w[n][1] = rw1;
            s_w[n][2] = rw2; s_w[n][3] = rw3;

            rxi = (int)fmaxf(fminf(x0f, 1.0e8f), -1.0e8f);
            ryi = (int)fmaxf(fminf(y0f, 1.0e8f), -1.0e8f);
            int bnC = (b * Nc + n) * Cc;
            mk_meta4<H0, W0>(bnC, x0f, y0f, rxi, ryi,
                             s_off[n][0], s_i0[n][0], s_spo[n][0], s_flags[n][0]);
            mk_meta4<H1, W1>(bnC, x0f, y0f, rxi, ryi,
                             s_off[n][1], s_i0[n][1], s_spo[n][1], s_flags[n][1]);
        } else {
            s_flags[n][0] = 0; s_flags[n][1] = 0;
        }
    }
    __syncthreads();

    int cnt = s_valid[0] + s_valid[1] + s_valid[2]
            + s_valid[3] + s_valid[4] + s_valid[5];
    float inv = __fdividef(0.25f, (float)cnt + EPSF);

    // export metadata (prescaled weights) for the staging kernels
    if (c < Nc) {
        int idx = bm * Nc + c;
        float4 wv, xv;
        wv.x = rw0 * inv; wv.y = rw1 * inv; wv.z = rw2 * inv; wv.w = rw3 * inv;
        xv.x = __int_as_float(rxi);
        xv.y = __int_as_float(ryi);
        xv.z = rvalid ? 1.0f : 0.0f;
        xv.w = 0.0f;
        g_meta_w[idx] = wv;
        g_meta_x[idx] = xv;
    }

    // L0 + L1 gathers
    float acc = 0.0f;
    #pragma unroll
    for (int n = 0; n < Nc; n++) {
        if (!s_valid[n]) continue;   // warp-uniform
        float w00 = s_w[n][0], w10 = s_w[n][1];
        float w01 = s_w[n][2], w11 = s_w[n][3];
        acc += use_meta4<H0, W0>(f0, c, s_off[n][0], s_i0[n][0], s_spo[n][0],
                                 s_flags[n][0], w00, w10, w01, w11);
        acc += use_meta4<H1, W1>(f1, c, s_off[n][1], s_i0[n][1], s_spo[n][1],
                                 s_flags[n][1], w00, w10, w01, w11);
    }

    out[bm * Cc + c] = acc * inv;   // B kernels atomicAdd L2/L3 on top
}

// =========================================================================
//  Kernel B: smem-staged gather for one small level
//  grid = Bq * Nc * (Cc / CG); block = 256 = QPAR queries x CG channels
// =========================================================================
template <int CG, int H, int W, int STRIDE>
__global__ void __launch_bounds__(256)
stage_kernel(const float* __restrict__ f, float* __restrict__ out)
{
    extern __shared__ float sm[];
    constexpr int PLANE = H * W;
    constexpr int QPAR  = 256 / CG;
    constexpr int NCG   = Cc / CG;

    int bid = blockIdx.x;
    int cg  = bid % NCG;
    int n   = (bid / NCG) % Nc;
    int b   = bid / (NCG * Nc);
    int tid = threadIdx.x;

    // ---- stage the channel slice (fully coalesced, sectors 100% used) ----
    const float* src = f + ((long long)((b * Nc + n) * Cc + cg * CG)) * PLANE;
    #pragma unroll 4
    for (int ch = 0; ch < CG; ch++) {
        for (int px = tid; px < PLANE; px += 256)
            sm[ch * STRIDE + px] = __ldg(src + ch * PLANE + px);
    }
    __syncthreads();

    int ch = tid % CG;              // lanes map to consecutive channels
    int qo = tid / CG;              // warp-uniform query offset

    const float4* mw = g_meta_w + (b * Mq) * Nc + n;
    const float4* mx = g_meta_x + (b * Mq) * Nc + n;
    float* ob = out + (b * Mq) * Cc + cg * CG + ch;

    for (int m = qo; m < Mq; m += QPAR) {
        float4 xv = __ldg(mx + m * Nc);          // broadcast
        if (xv.z == 0.0f) continue;              // invalid camera (uniform)
        int xi = __float_as_int(xv.x);
        int yi = __float_as_int(xv.y);

        bool bx0 = (xi >=  0) & (xi <= W - 1);
        bool bx1 = (xi >= -1) & (xi <= W - 2);
        bool by0 = (yi >=  0) & (yi <= H - 1);
        bool by1 = (yi >= -1) & (yi <= H - 2);
        if (!((bx0 | bx1) & (by0 | by1))) continue;   // fully OOB (uniform)

        float4 wv = __ldg(mw + m * Nc);          // broadcast, prescaled
        const float* p = sm + ch * STRIDE + yi * W + xi;
        float v = 0.0f;
        if (by0 & bx0) v += wv.x * p[0];
        if (by0 & bx1) v += wv.y * p[1];
        if (by1 & bx0) v += wv.z * p[W];
        if (by1 & bx1) v += wv.w * p[W + 1];

        atomicAdd(ob + m * Cc, v);
    }
}

// =========================================================================
//  Host
// =========================================================================
#define CG2 32
#define ST2 (H2 * W2 + 1)            // 1451, odd -> conflict-free
#define SMEM_B2 (CG2 * ST2 * 4)      // 185,728 B

#define CG3 64
#define ST3 (H3 * W3)                // 375, already odd
#define SMEM_B3 (CG3 * ST3 * 4)      // 96,000 B

extern "C" void kernel_launch(void* const* d_in, const int* in_sizes, int n_in,
                              void* d_out, int out_size)
{
    const float* f0   = (const float*)d_in[0];
    const float* f1   = (const float*)d_in[1];
    const float* f2   = (const float*)d_in[2];
    const float* f3   = (const float*)d_in[3];
    const float* refp = (const float*)d_in[4];
    const float* l2i  = (const float*)d_in[5];
    float* out = (float*)d_out;

    static bool attr_set = false;
    if (!attr_set) {
        cudaFuncSetAttribute(stage_kernel<CG2, H2, W2, ST2>,
                             cudaFuncAttributeMaxDynamicSharedMemorySize, SMEM_B2);
        cudaFuncSetAttribute(stage_kernel<CG3, H3, W3, ST3>,
                             cudaFuncAttributeMaxDynamicSharedMemorySize, SMEM_B3);
        attr_set = true;
    }

    kernelA<<<Bq * Mq, Cc>>>(f0, f1, refp, l2i, out);
    stage_kernel<CG2, H2, W2, ST2><<<Bq * Nc * (Cc / CG2), 256, SMEM_B2>>>(f2, out);
    stage_kernel<CG3, H3, W3, ST3><<<Bq * Nc * (Cc / CG3), 256, SMEM_B3>>>(f3, out);
}

// round 8
// speedup vs baseline: 2.8739x; 2.8739x over previous
#include <cuda_runtime.h>
#include <cuda.h>
#include <math.h>
#include <stdint.h>

// Problem constants (fixed by the dataset)
#define Bq   2
#define Nc   6
#define Cc   256
#define Mq   900
#define EPSF 1e-5f

#define H0 116
#define W0 200
#define H1 58
#define W1 100
#define H2 29
#define W2 50
#define H3 15
#define W3 25

// TMA tile: box (4, 2, 256) fp32 = 8KB. Two tiles (L0, L1) per camera.
#define TILE_FLOATS 2048
#define SMEM_DYN (Nc * 2 * TILE_FLOATS * 4 + 1024 + 128)

// ---------------- PTX helpers ----------------
__device__ __forceinline__ uint32_t smem_u32(const void* p) {
    uint32_t a;
    asm("{ .reg .u64 t; cvta.to.shared.u64 t, %1; cvt.u32.u64 %0, t; }" : "=r"(a) : "l"(p));
    return a;
}
#define MBAR_INIT(addr, cnt) \
    asm volatile("mbarrier.init.shared.b64 [%0], %1;" :: "r"(addr), "r"(cnt) : "memory")
#define FENCE_ASYNC_SHARED() \
    asm volatile("fence.proxy.async.shared::cta;" ::: "memory")
#define MBAR_EXPECT_TX(addr, bytes) \
    asm volatile("mbarrier.arrive.expect_tx.shared.b64 _, [%0], %1;" :: "r"(addr), "r"(bytes) : "memory")
#define MBAR_WAIT(addr, parity) do {                                            \
    uint32_t _m = (addr); uint32_t _p = (parity); uint32_t _d;                  \
    asm volatile("{\n\t.reg .pred p;\n\t"                                       \
        "mbarrier.try_wait.parity.acquire.cta.shared::cta.b64 p, [%1], %2;\n\t" \
        "selp.b32 %0, 1, 0, p;\n\t}"                                            \
        : "=r"(_d) : "r"(_m), "r"(_p) : "memory");                              \
    if (!_d) {                                                                  \
        asm volatile("{\n\t.reg .pred P1;\n\t"                                  \
            "W_%=:\n\t"                                                         \
            "mbarrier.try_wait.parity.acquire.cta.shared::cta.b64 P1, [%0], %1, 0x989680;\n\t" \
            "@P1 bra.uni D_%=;\n\t"                                             \
            "bra.uni W_%=;\n\t"                                                 \
            "D_%=:\n\t}"                                                        \
            :: "r"(_m), "r"(_p) : "memory");                                    \
    }                                                                           \
} while (0)
#define TMA_3D(smem, tmap, x, y, z, mbar)                                       \
    asm volatile("cp.async.bulk.tensor.3d.shared::cta.global.tile.mbarrier::complete_tx::bytes " \
        "[%0], [%1, {%2, %3, %4}], [%5];"                                       \
        :: "r"(smem), "l"(tmap), "r"(x), "r"(y), "r"(z), "r"(mbar) : "memory")

// ---------------- f2/f3 LDG path (proven in round 5) ----------------
__device__ __forceinline__ float pick2(float2 q, int i) { return (i == 0) ? q.x : q.y; }
__device__ __forceinline__ float pick4(float4 q, int i)
{
    float r = q.w;
    r = (i == 2) ? q.z : r;
    r = (i == 1) ? q.y : r;
    r = (i == 0) ? q.x : r;
    return r;
}

template <int H, int W, int V>
__device__ __forceinline__ void mk_meta(int bnC, float x0f, float y0f,
                                        int xi, int yi,
                                        int& off, int& i0o, int& spo, int& flags)
{
    bool bx0 = (x0f >= 0.0f)  & (x0f <= (float)(W - 1));
    bool bx1 = (x0f >= -1.0f) & (x0f <= (float)(W - 2));
    bool by0 = (y0f >= 0.0f)  & (y0f <= (float)(H - 1));
    bool by1 = (y0f >= -1.0f) & (y0f <= (float)(H - 2));

    if (V == 1) {
        off   = bnC * (H * W) + yi * W + xi;
        flags = ((by0 & bx0) ? 1 : 0) | ((by0 & bx1) ? 2 : 0)
              | ((by1 & bx0) ? 4 : 0) | ((by1 & bx1) ? 8 : 0);
        i0o = 0; spo = 0;
    } else {
        int a = xi & ~(V - 1);
        a = (a < 0) ? 0 : a;
        a = (a > W - V) ? (W - V) : a;
        int  i0   = xi - a;
        bool sp   = (i0 >= V - 1);
        bool bxv  = bx1 & !sp;
        bool anyx = bx0 | bxv;
        bool spu  = bx1 & sp;
        int f = 0;
        f |= (by0 & anyx) ? 1  : 0;
        f |= (by1 & anyx) ? 2  : 0;
        f |= bx0          ? 4  : 0;
        f |= bxv          ? 8  : 0;
        f |= (spu & by0)  ? 16 : 0;
        f |= (spu & by1)  ? 32 : 0;
        flags = f;
        off = bnC * (H * W) + yi * W + a;
        i0o = i0;
        spo = bnC * (H * W) + yi * W + xi + 1;
    }
}

template <int H, int W, int V>
__device__ __forceinline__ float use_meta(const float* __restrict__ f, int c,
                                          int off, int i0, int spo, int flags,
                                          float w00, float w10, float w01, float w11)
{
    float v = 0.0f;
    const float* p = f + c * (H * W) + off;
    if (V == 2) {
        if (flags & 1) {
            float2 q = __ldg((const float2*)p);
            if (flags & 4) v += w00 * pick2(q, i0);
            if (flags & 8) v += w10 * pick2(q, i0 + 1);
        }
        if (flags & 2) {
            float2 q = __ldg((const float2*)(p + W));
            if (flags & 4) v += w01 * pick2(q, i0);
            if (flags & 8) v += w11 * pick2(q, i0 + 1);
        }
        if (flags & 16) v += w10 * __ldg(f + c * (H * W) + spo);
        if (flags & 32) v += w11 * __ldg(f + c * (H * W) + spo + W);
    } else {
        if (flags & 1) v += w00 * __ldg(p);
        if (flags & 2) v += w10 * __ldg(p + 1);
        if (flags & 4) v += w01 * __ldg(p + W);
        if (flags & 8) v += w11 * __ldg(p + W + 1);
    }
    return v;
}

// ---------------- kernel ----------------
__global__ void __launch_bounds__(Cc)
feature_sampler_tma_kernel(const __grid_constant__ CUtensorMap tm0,
                           const __grid_constant__ CUtensorMap tm1,
                           const float* __restrict__ f0,
                           const float* __restrict__ f1,
                           const float* __restrict__ f2,
                           const float* __restrict__ f3,
                           const float* __restrict__ refp,
                           const float* __restrict__ l2i,
                           float* __restrict__ out)
{
    extern __shared__ char dsm_raw[];
    float* dsm = (float*)(((uintptr_t)dsm_raw + 1023) & ~(uintptr_t)1023);

    __shared__ float s_w[Nc][4];
    __shared__ int   s_valid[Nc], s_xa[Nc], s_yi[Nc], s_i0[Nc];
    __shared__ int   s_spm[Nc];                 // spill predicates b0..b3
    __shared__ int   s_spo0[Nc], s_spo1[Nc];    // in-plane offset of (y0, x1)
    __shared__ int   s_off2[Nc], s_i02[Nc], s_spo2[Nc], s_fl2[Nc];
    __shared__ int   s_off3[Nc], s_fl3[Nc];
    __shared__ unsigned long long s_mbar[Nc];

    int bm = blockIdx.x;
    int b  = bm / Mq;
    int c  = threadIdx.x;

    // ---------- phase 1: per-camera metadata (threads 0..5) ----------
    if (c < Nc) {
        int n = c;
        const float* rp = refp + bm * 3;
        float rx = rp[0] * 122.4f - 61.2f;
        float ry = rp[1] * 122.4f - 61.2f;
        float rz = rp[2] * 20.0f  - 10.0f;

        const float* Mt = l2i + (b * Nc + n) * 16;
        float c0 = Mt[0] * rx + Mt[1] * ry + Mt[2]  * rz + Mt[3];
        float c1 = Mt[4] * rx + Mt[5] * ry + Mt[6]  * rz + Mt[7];
        float c2 = Mt[8] * rx + Mt[9] * ry + Mt[10] * rz + Mt[11];

        bool valid = (c2 > EPSF);
        s_valid[n] = valid ? 1 : 0;

        if (valid) {
            float rcp = __fdividef(1.0f, c2 + EPSF);
            // grid-sample normalization cancels: pixel = p - 0.5 at EVERY level
            float x = c0 * rcp - 0.5f;
            float y = c1 * rcp - 0.5f;
            float x0f = floorf(x);
            float y0f = floorf(y);
            float wx1 = x - x0f, wx0 = 1.0f - wx1;
            float wy1 = y - y0f, wy0 = 1.0f - wy1;
            s_w[n][0] = wx0 * wy0;
            s_w[n][1] = wx1 * wy0;
            s_w[n][2] = wx0 * wy1;
            s_w[n][3] = wx1 * wy1;

            int xi = (int)fmaxf(fminf(x0f, 1.0e8f), -1.0e8f);
            int yi = (int)fmaxf(fminf(y0f, 1.0e8f), -1.0e8f);
            // clamp to a small envelope: identity whenever any corner is
            // in-bounds for ANY level; keeps TMA coordinates tiny and still
            // fully-OOB (zero-fill) when the raw coords were wild.
            xi = min(max(xi, -8), 256);
            yi = min(max(yi, -8), 160);

            int xa = xi & ~3;            // 16B-aligned box start (neg-safe)
            s_xa[n] = xa;
            s_yi[n] = yi;
            s_i0[n] = xi - xa;           // 0..3; 3 => x1 spills out of box

            float x0c = (float)xi, y0c = (float)yi;   // == x0f in valid range
            bool l0bx1 = (x0c >= -1.0f) & (x0c <= (float)(W0 - 2));
            bool l0by0 = (y0c >= 0.0f)  & (y0c <= (float)(H0 - 1));
            bool l0by1 = (y0c >= -1.0f) & (y0c <= (float)(H0 - 2));
            bool l1bx1 = (x0c >= -1.0f) & (x0c <= (float)(W1 - 2));
            bool l1by0 = (y0c >= 0.0f)  & (y0c <= (float)(H1 - 1));
            bool l1by1 = (y0c >= -1.0f) & (y0c <= (float)(H1 - 2));
            s_spm[n] = ((l0bx1 & l0by0) ? 1 : 0) | ((l0bx1 & l0by1) ? 2 : 0)
                     | ((l1bx1 & l1by0) ? 4 : 0) | ((l1bx1 & l1by1) ? 8 : 0);
            s_spo0[n] = yi * W0 + xi + 1;
            s_spo1[n] = yi * W1 + xi + 1;

            int bnC = (b * Nc + n) * Cc;
            mk_meta<H2, W2, 2>(bnC, x0f, y0f, xi, yi, s_off2[n], s_i02[n], s_spo2[n], s_fl2[n]);
            int d0, d1;
            mk_meta<H3, W3, 1>(bnC, x0f, y0f, xi, yi, s_off3[n], d0, d1, s_fl3[n]);
        } else {
            s_fl2[n] = 0; s_fl3[n] = 0; s_spm[n] = 0;
        }
    }
    if (c == 0) {
        #pragma unroll
        for (int n = 0; n < Nc; n++) MBAR_INIT(smem_u32(&s_mbar[n]), 1);
        FENCE_ASYNC_SHARED();
    }
    __syncthreads();

    // ---------- phase 1b: thread 0 issues all TMA loads ----------
    if (c == 0) {
        #pragma unroll
        for (int n = 0; n < Nc; n++) {
            if (!s_valid[n]) continue;
            uint32_t mb = smem_u32(&s_mbar[n]);
            MBAR_EXPECT_TX(mb, 2 * TILE_FLOATS * 4);
            int xa = s_xa[n], yi = s_yi[n], zc = (b * Nc + n) * Cc;
            uint32_t t0 = smem_u32(&dsm[(n * 2 + 0) * TILE_FLOATS]);
            uint32_t t1 = smem_u32(&dsm[(n * 2 + 1) * TILE_FLOATS]);
            TMA_3D(t0, &tm0, xa, yi, zc, mb);
            TMA_3D(t1, &tm1, xa, yi, zc, mb);
        }
    }

    // ---------- phase 2a: f2/f3 LDG gathers (overlap TMA arrival) ----------
    float acc = 0.0f;
    int cnt = 0;
    #pragma unroll
    for (int n = 0; n < Nc; n++) {
        int valid = s_valid[n];
        cnt += valid;
        if (!valid) continue;
        float w00 = s_w[n][0], w10 = s_w[n][1], w01 = s_w[n][2], w11 = s_w[n][3];
        acc += use_meta<H2, W2, 2>(f2, c, s_off2[n], s_i02[n], s_spo2[n], s_fl2[n], w00, w10, w01, w11);
        acc += use_meta<H3, W3, 1>(f3, c, s_off3[n], 0, 0, s_fl3[n], w00, w10, w01, w11);
    }

    // ---------- phase 2b: consume TMA tiles for L0/L1 ----------
    #pragma unroll
    for (int n = 0; n < Nc; n++) {
        if (!s_valid[n]) continue;
        MBAR_WAIT(smem_u32(&s_mbar[n]), 0);

        const float4* t0 = (const float4*)&dsm[(n * 2 + 0) * TILE_FLOATS];
        const float4* t1 = (const float4*)&dsm[(n * 2 + 1) * TILE_FLOATS];
        int i0 = s_i0[n];                 // warp-uniform

        float4 ar0 = t0[c * 2];           // L0 row y0, cols xa..xa+3
        float4 ar1 = t0[c * 2 + 1];       // L0 row y1
        float4 br0 = t1[c * 2];           // L1 row y0
        float4 br1 = t1[c * 2 + 1];       // L1 row y1

        float a00 = pick4(ar0, i0), a01 = pick4(ar0, i0 + 1);
        float a10 = pick4(ar1, i0), a11 = pick4(ar1, i0 + 1);
        float b00 = pick4(br0, i0), b01 = pick4(br0, i0 + 1);
        float b10 = pick4(br1, i0), b11 = pick4(br1, i0 + 1);

        if (i0 == 3) {                    // x1 column spilled out of the box
            int sm = s_spm[n];
            int pl0 = ((b * Nc + n) * Cc + c) * (H0 * W0);
            int pl1 = ((b * Nc + n) * Cc + c) * (H1 * W1);
            a01 = (sm & 1) ? __ldg(f0 + pl0 + s_spo0[n])      : 0.0f;
            a11 = (sm & 2) ? __ldg(f0 + pl0 + s_spo0[n] + W0) : 0.0f;
            b01 = (sm & 4) ? __ldg(f1 + pl1 + s_spo1[n])      : 0.0f;
            b11 = (sm & 8) ? __ldg(f1 + pl1 + s_spo1[n] + W1) : 0.0f;
        }

        float w00 = s_w[n][0], w10 = s_w[n][1], w01 = s_w[n][2], w11 = s_w[n][3];
        acc += w00 * (a00 + b00) + w10 * (a01 + b01)
             + w01 * (a10 + b10) + w11 * (a11 + b11);
    }

    float inv = __fdividef(0.25f, (float)cnt + EPSF);
    out[bm * Cc + c] = acc * inv;
}

// ---------------- host ----------------
typedef CUresult (*PFN_encodeTiled)(CUtensorMap*, CUtensorMapDataType, cuuint32_t, void*,
                                    const cuuint64_t*, const cuuint64_t*,
                                    const cuuint32_t*, const cuuint32_t*,
                                    CUtensorMapInterleave, CUtensorMapSwizzle,
                                    CUtensorMapL2promotion, CUtensorMapFloatOOBfill);

static void build_map(PFN_encodeTiled enc, CUtensorMap* tm, const void* base, int H, int W)
{
    cuuint64_t dims[3]    = {(cuuint64_t)W, (cuuint64_t)H, (cuuint64_t)(Bq * Nc * Cc)};
    cuuint64_t strides[2] = {(cuuint64_t)W * 4, (cuuint64_t)H * W * 4};
    cuuint32_t box[3]     = {4, 2, 256};
    cuuint32_t estr[3]    = {1, 1, 1};
    enc(tm, CU_TENSOR_MAP_DATA_TYPE_FLOAT32, 3, (void*)base,
        dims, strides, box, estr,
        CU_TENSOR_MAP_INTERLEAVE_NONE, CU_TENSOR_MAP_SWIZZLE_NONE,
        CU_TENSOR_MAP_L2_PROMOTION_L2_128B, CU_TENSOR_MAP_FLOAT_OOB_FILL_NONE);
}

extern "C" void kernel_launch(void* const* d_in, const int* in_sizes, int n_in,
                              void* d_out, int out_size)
{
    const float* f0   = (const float*)d_in[0];
    const float* f1   = (const float*)d_in[1];
    const float* f2   = (const float*)d_in[2];
    const float* f3   = (const float*)d_in[3];
    const float* refp = (const float*)d_in[4];
    const float* l2i  = (const float*)d_in[5];
    float* out = (float*)d_out;

    static PFN_encodeTiled enc = nullptr;
    if (!enc) {
        void* p = nullptr;
        cudaDriverEntryPointQueryResult st;
        cudaGetDriverEntryPoint("cuTensorMapEncodeTiled", &p, cudaEnableDefault, &st);
        enc = (PFN_encodeTiled)p;
    }
    CUtensorMap tm0, tm1;
    build_map(enc, &tm0, f0, H0, W0);
    build_map(enc, &tm1, f1, H1, W1);

    static bool attr_set = false;
    if (!attr_set) {
        cudaFuncSetAttribute(feature_sampler_tma_kernel,
                             cudaFuncAttributeMaxDynamicSharedMemorySize, SMEM_DYN);
        attr_set = true;
    }

    feature_sampler_tma_kernel<<<Bq * Mq, Cc, SMEM_DYN>>>(tm0, tm1, f0, f1, f2, f3,
                                                          refp, l2i, out);
}

// round 9
// speedup vs baseline: 5.3523x; 1.8624x over previous
#include <cuda_runtime.h>
#include <math.h>

// Problem constants (fixed by the dataset)
#define Bq   2
#define Nc   6
#define Cc   256
#define Mq   900
#define EPSF 1e-5f

#define H0 116
#define W0 200
#define H1 58
#define W1 100
#define H2 29
#define W2 50
#define H3 15
#define W3 25

#define P2 (H2 * W2)     // 1450
#define P3 (H3 * W3)     // 375

#define NBM  (Bq * Mq)               // 1800 sampler blocks
#define NT2  (Bq * Nc * 8 * 46)      // 4416 f2 transpose tiles (8 ctiles x 46 ptiles)
#define NT3  (Bq * Nc * 8 * 12)      // 1152 f3 transpose tiles (8 x 12)

// ---------------- device scratch ----------------
__device__ float  g_f2t[Bq * Nc * P2 * Cc];   // pixel-major f2: [bn][px][c]
__device__ float  g_f3t[Bq * Nc * P3 * Cc];   // pixel-major f3
__device__ float4 g_mw[NBM * Nc];             // prescaled bilinear weights
__device__ int4   g_mi[NBM * Nc];             // {off2, off3, flags, 0}

// ---------------- L0/L1 vectorized gather (proven round-5/7 path) ----------
__device__ __forceinline__ float pick4(float4 q, int i)
{
    float r = q.w;
    r = (i == 2) ? q.z : r;
    r = (i == 1) ? q.y : r;
    r = (i == 0) ? q.x : r;
    return r;
}

template <int H, int W>
__device__ __forceinline__ void mk_meta4(int bnC, float x0f, float y0f,
                                         int xi, int yi,
                                         int& off, int& i0o, int& spo, int& flags)
{
    bool bx0 = (x0f >= 0.0f)  & (x0f <= (float)(W - 1));
    bool bx1 = (x0f >= -1.0f) & (x0f <= (float)(W - 2));
    bool by0 = (y0f >= 0.0f)  & (y0f <= (float)(H - 1));
    bool by1 = (y0f >= -1.0f) & (y0f <= (float)(H - 2));

    int a = xi & ~3;
    a = (a < 0) ? 0 : a;
    a = (a > W - 4) ? (W - 4) : a;
    int  i0   = xi - a;
    bool sp   = (i0 >= 3);
    bool bxv  = bx1 & !sp;
    bool anyx = bx0 | bxv;
    bool spu  = bx1 & sp;
    int f = 0;
    f |= (by0 & anyx) ? 1  : 0;
    f |= (by1 & anyx) ? 2  : 0;
    f |= bx0          ? 4  : 0;
    f |= bxv          ? 8  : 0;
    f |= (spu & by0)  ? 16 : 0;
    f |= (spu & by1)  ? 32 : 0;
    flags = f;
    off = bnC * (H * W) + yi * W + a;
    i0o = i0;
    spo = bnC * (H * W) + yi * W + xi + 1;
}

template <int H, int W>
__device__ __forceinline__ float use_meta4(const float* __restrict__ f, int c,
                                           int off, int i0, int spo, int flags,
                                           float w00, float w10, float w01, float w11)
{
    float v = 0.0f;
    const float* p = f + c * (H * W) + off;
    if (flags & 1) {
        float4 q = __ldg((const float4*)p);
        if (flags & 4) v += w00 * pick4(q, i0);
        if (flags & 8) v += w10 * pick4(q, i0 + 1);
    }
    if (flags & 2) {
        float4 q = __ldg((const float4*)(p + W));
        if (flags & 4) v += w01 * pick4(q, i0);
        if (flags & 8) v += w11 * pick4(q, i0 + 1);
    }
    if (flags & 16) v += w10 * __ldg(f + c * (H * W) + spo);
    if (flags & 32) v += w11 * __ldg(f + c * (H * W) + spo + W);
    return v;
}

// 4-bit corner flags for one level (q00, q10, q01, q11)
template <int H, int W>
__device__ __forceinline__ int corner_flags(float x0f, float y0f)
{
    bool bx0 = (x0f >= 0.0f)  & (x0f <= (float)(W - 1));
    bool bx1 = (x0f >= -1.0f) & (x0f <= (float)(W - 2));
    bool by0 = (y0f >= 0.0f)  & (y0f <= (float)(H - 1));
    bool by1 = (y0f >= -1.0f) & (y0f <= (float)(H - 2));
    return ((by0 & bx0) ? 1 : 0) | ((by0 & bx1) ? 2 : 0)
         | ((by1 & bx0) ? 4 : 0) | ((by1 & bx1) ? 8 : 0);
}

// ---------------- tiled 32x32 transpose: [C][P] -> [P][C] ----------------
template <int P>
__device__ __forceinline__ void transpose_plane(const float* __restrict__ src,
                                                float* __restrict__ dst,
                                                int ctile, int ptile,
                                                int tx, int ty)
{
    __shared__ float tile[32][33];
    int cb = ctile * 32, pb = ptile * 32;
    #pragma unroll
    for (int j = 0; j < 4; j++) {
        int cc = cb + ty + j * 8;
        int pp = pb + tx;
        tile[ty + j * 8][tx] = (pp < P) ? __ldg(src + cc * P + pp) : 0.0f;
    }
    __syncthreads();
    #pragma unroll
    for (int j = 0; j < 4; j++) {
        int pp = pb + ty + j * 8;
        if (pp < P) dst[pp * Cc + cb + tx] = tile[tx][ty + j * 8];
    }
}

// =========================================================================
//  Kernel 1: [0,NBM)           sampler blocks: L0+L1 gather + meta export
//            [NBM, NBM+NT2)    f2 transpose tiles
//            [.., +NT3)        f3 transpose tiles
// =========================================================================
__global__ void __launch_bounds__(Cc)
kernel1(const float* __restrict__ f0,
        const float* __restrict__ f1,
        const float* __restrict__ f2,
        const float* __restrict__ f3,
        const float* __restrict__ refp,
        const float* __restrict__ l2i,
        float* __restrict__ out)
{
    int bid = blockIdx.x;

    if (bid >= NBM) {                      // ---------- transpose blocks ----------
        int tx = threadIdx.x & 31, ty = threadIdx.x >> 5;
        int t = bid - NBM;
        if (t < NT2) {
            int bn = t / (8 * 46);
            int r  = t % (8 * 46);
            transpose_plane<P2>(f2 + bn * Cc * P2, g_f2t + bn * P2 * Cc,
                                r / 46, r % 46, tx, ty);
        } else {
            t -= NT2;
            int bn = t / (8 * 12);
            int r  = t % (8 * 12);
            transpose_plane<P3>(f3 + bn * Cc * P3, g_f3t + bn * P3 * Cc,
                                r / 12, r % 12, tx, ty);
        }
        return;
    }

    // ---------- sampler block (round-7 kernelA + extended meta) ----------
    __shared__ int   s_valid[Nc];
    __shared__ float s_w[Nc][4];
    __shared__ int   s_off[Nc][2], s_i0[Nc][2], s_spo[Nc][2], s_flags[Nc][2];

    int bm = bid;
    int b  = bm / Mq;
    int c  = threadIdx.x;

    float rw0 = 0, rw1 = 0, rw2 = 0, rw3 = 0;
    int   roff2 = 0, roff3 = 0, rfl = 0;

    if (c < Nc) {
        int n = c;
        const float* rp = refp + bm * 3;
        float rx = rp[0] * 122.4f - 61.2f;
        float ry = rp[1] * 122.4f - 61.2f;
        float rz = rp[2] * 20.0f  - 10.0f;

        const float* Mt = l2i + (b * Nc + n) * 16;
        float c0 = Mt[0] * rx + Mt[1] * ry + Mt[2]  * rz + Mt[3];
        float c1 = Mt[4] * rx + Mt[5] * ry + Mt[6]  * rz + Mt[7];
        float c2 = Mt[8] * rx + Mt[9] * ry + Mt[10] * rz + Mt[11];

        int valid = (c2 > EPSF) ? 1 : 0;
        s_valid[n] = valid;

        if (valid) {
            float rcp = __fdividef(1.0f, c2 + EPSF);
            // grid-sample normalization cancels: pixel = p - 0.5 at EVERY level
            float x = c0 * rcp - 0.5f;
            float y = c1 * rcp - 0.5f;
            float x0f = floorf(x);
            float y0f = floorf(y);
            float wx1 = x - x0f, wx0 = 1.0f - wx1;
            float wy1 = y - y0f, wy0 = 1.0f - wy1;
            rw0 = wx0 * wy0; rw1 = wx1 * wy0;
            rw2 = wx0 * wy1; rw3 = wx1 * wy1;
            s_w[n][0] = rw0; s_w[n][1] = rw1;
            s_w[n][2] = rw2; s_w[n][3] = rw3;

            int xi = (int)fmaxf(fminf(x0f, 1.0e8f), -1.0e8f);
            int yi = (int)fmaxf(fminf(y0f, 1.0e8f), -1.0e8f);
            int bnC = (b * Nc + n) * Cc;
            mk_meta4<H0, W0>(bnC, x0f, y0f, xi, yi,
                             s_off[n][0], s_i0[n][0], s_spo[n][0], s_flags[n][0]);
            mk_meta4<H1, W1>(bnC, x0f, y0f, xi, yi,
                             s_off[n][1], s_i0[n][1], s_spo[n][1], s_flags[n][1]);

            // f2t / f3t meta (pixel-major). Clamp so offsets stay small; the
            // clamp is identity whenever any corner flag is set.
            rfl = corner_flags<H2, W2>(x0f, y0f)
                | (corner_flags<H3, W3>(x0f, y0f) << 4);
            int xc = min(max(xi, -4), 64);
            int yc = min(max(yi, -4), 40);
            int bn = b * Nc + n;
            roff2 = (bn * P2 + yc * W2 + xc) * Cc;
            roff3 = (bn * P3 + yc * W3 + xc) * Cc;
        } else {
            s_flags[n][0] = 0; s_flags[n][1] = 0;
        }
    }
    __syncthreads();

    int cnt = s_valid[0] + s_valid[1] + s_valid[2]
            + s_valid[3] + s_valid[4] + s_valid[5];
    float inv = __fdividef(0.25f, (float)cnt + EPSF);

    if (c < Nc) {
        int idx = bm * Nc + c;
        float4 wv;
        wv.x = rw0 * inv; wv.y = rw1 * inv;
        wv.z = rw2 * inv; wv.w = rw3 * inv;
        g_mw[idx] = wv;
        int4 iv; iv.x = roff2; iv.y = roff3; iv.z = rfl; iv.w = 0;
        g_mi[idx] = iv;
    }

    float acc = 0.0f;
    #pragma unroll
    for (int n = 0; n < Nc; n++) {
        if (!s_valid[n]) continue;   // warp-uniform
        float w00 = s_w[n][0], w10 = s_w[n][1];
        float w01 = s_w[n][2], w11 = s_w[n][3];
        acc += use_meta4<H0, W0>(f0, c, s_off[n][0], s_i0[n][0], s_spo[n][0],
                                 s_flags[n][0], w00, w10, w01, w11);
        acc += use_meta4<H1, W1>(f1, c, s_off[n][1], s_i0[n][1], s_spo[n][1],
                                 s_flags[n][1], w00, w10, w01, w11);
    }

    out[bm * Cc + c] = acc * inv;    // kernel2 adds f2/f3 on top
}

// =========================================================================
//  Kernel 2: f2/f3 sampling from pixel-major copies (fully coalesced)
// =========================================================================
__global__ void __launch_bounds__(Cc)
kernel2(float* __restrict__ out)
{
    int bm = blockIdx.x;
    int c  = threadIdx.x;

    float acc = 0.0f;
    #pragma unroll
    for (int n = 0; n < Nc; n++) {
        int4 iv = g_mi[bm * Nc + n];          // broadcast
        int fl = iv.z;
        if (!fl) continue;                    // warp-uniform
        float4 wv = g_mw[bm * Nc + n];

        const float* p2 = g_f2t + iv.x + c;
        if (fl & 1) acc += wv.x * __ldg(p2);
        if (fl & 2) acc += wv.y * __ldg(p2 + Cc);
        if (fl & 4) acc += wv.z * __ldg(p2 + W2 * Cc);
        if (fl & 8) acc += wv.w * __ldg(p2 + (W2 + 1) * Cc);

        const float* p3 = g_f3t + iv.y + c;
        if (fl & 16)  acc += wv.x * __ldg(p3);
        if (fl & 32)  acc += wv.y * __ldg(p3 + Cc);
        if (fl & 64)  acc += wv.z * __ldg(p3 + W3 * Cc);
        if (fl & 128) acc += wv.w * __ldg(p3 + (W3 + 1) * Cc);
    }

    out[bm * Cc + c] += acc;
}

// ---------------- host ----------------
extern "C" void kernel_launch(void* const* d_in, const int* in_sizes, int n_in,
                              void* d_out, int out_size)
{
    const float* f0   = (const float*)d_in[0];
    const float* f1   = (const float*)d_in[1];
    const float* f2   = (const float*)d_in[2];
    const float* f3   = (const float*)d_in[3];
    const float* refp = (const float*)d_in[4];
    const float* l2i  = (const float*)d_in[5];
    float* out = (float*)d_out;

    kernel1<<<NBM + NT2 + NT3, Cc>>>(f0, f1, f2, f3, refp, l2i, out);
    kernel2<<<NBM, Cc>>>(out);
}